// round 12
// baseline (speedup 1.0000x reference)
#include <cuda_runtime.h>
#include <math.h>

#define NMAX  8192
#define NBKT  1024
#define TPB   448     // 14 warps; 1 warp = 4 rows
#define WPC   14
#define GMAX  512

__device__ float2 st_uz[NMAX];        // sorted-by-yt: (u = yp*20*log2e, z = -u*yt)
__device__ float  st_yt[NMAX];        // sorted yt
__device__ int    g_boff[NBKT + 1];   // bucket rank offsets
__device__ float  g_ymin;
__device__ float2 g_part[GMAX];
__device__ int    g_done;             // zero-init; reset by last block each run

__device__ __forceinline__ float ex2a(float x) {
    float r; asm("ex2.approx.f32 %0, %1;" : "=f"(r) : "f"(x)); return r;
}

// ------------- Prep: counting sort staged through smem ----------------------
__global__ void __launch_bounds__(1024) pro_prep(const float* __restrict__ pred,
                                                 const float* __restrict__ ytg,
                                                 int n, int padn)
{
    __shared__ int   HA[NBKT], HB[NBKT];   // 8 KB
    __shared__ float SG[NMAX];             // 32 KB stage
    __shared__ float smn[32];
    const float K1 = 28.853900817779268f;  // 20 * log2(e)
    int t = threadIdx.x;

    HA[t] = 0;
    __syncthreads();

    float ry[8], rp[8];
    int   rb[8], rpos[8];
    float mn = 1e30f;

    #pragma unroll
    for (int e = 0; e < 8; e++) {
        int i = t + e * 1024;
        if (i < n) {
            float y = ytg[i], p = pred[i];
            ry[e] = y; rp[e] = p;
            int b = min(NBKT - 1, max(0, (int)floorf(y * (float)NBKT)));
            rb[e] = b;
            atomicAdd(&HA[b], 1);
            mn = fminf(mn, y);
        } else { ry[e] = 0.f; rp[e] = 0.f; rb[e] = -1; }
    }
    __syncthreads();

    int* pa = HA; int* pb = HB;
    #pragma unroll
    for (int off = 1; off < NBKT; off <<= 1) {
        pb[t] = pa[t] + ((t >= off) ? pa[t - off] : 0);
        __syncthreads();
        int* tmp = pa; pa = pb; pb = tmp;
    }
    if (t == 0) g_boff[0] = 0;
    g_boff[t + 1] = pa[t];
    pb[t] = (t > 0) ? pa[t - 1] : 0;       // per-bucket running cursors
    __syncthreads();

    #pragma unroll
    for (int e = 0; e < 8; e++)
        if (rb[e] >= 0) rpos[e] = atomicAdd(&pb[rb[e]], 1);
    __syncthreads();

    float* uzf = (float*)st_uz;
    // pass 1: u (interleaved slot .x)
    #pragma unroll
    for (int e = 0; e < 8; e++) if (rb[e] >= 0) SG[rpos[e]] = rp[e] * K1;
    __syncthreads();
    #pragma unroll
    for (int e = 0; e < 8; e++) { int i = t + e * 1024; if (i < n) uzf[2 * i] = SG[i]; }
    __syncthreads();
    // pass 2: z = -u*yt (interleaved slot .y)
    #pragma unroll
    for (int e = 0; e < 8; e++) if (rb[e] >= 0) SG[rpos[e]] = -(rp[e] * K1) * ry[e];
    __syncthreads();
    #pragma unroll
    for (int e = 0; e < 8; e++) { int i = t + e * 1024; if (i < n) uzf[2 * i + 1] = SG[i]; }
    __syncthreads();
    // pass 3: yt
    #pragma unroll
    for (int e = 0; e < 8; e++) if (rb[e] >= 0) SG[rpos[e]] = ry[e];
    __syncthreads();
    #pragma unroll
    for (int e = 0; e < 8; e++) { int i = t + e * 1024; if (i < n) st_yt[i] = SG[i]; }
    // padding
    for (int i = n + t; i < padn; i += 1024) {
        uzf[2 * i] = 0.f; uzf[2 * i + 1] = 0.f; st_yt[i] = 1e30f;
    }

    // global min
    #pragma unroll
    for (int o = 16; o; o >>= 1) mn = fminf(mn, __shfl_xor_sync(0xffffffffu, mn, o));
    if ((t & 31) == 0) smn[t >> 5] = mn;
    __syncthreads();
    if (t < 32) {
        float v = smn[t];
        #pragma unroll
        for (int o = 16; o; o >>= 1) v = fminf(v, __shfl_xor_sync(0xffffffffu, v, o));
        if (t == 0) g_ymin = v;
    }
}

// ------------- Main: 4 rows per warp, nested fast regions --------------------
__global__ void __launch_bounds__(TPB) pro_main(float* __restrict__ out,
                                                int n, int grid)
{
    __shared__ float rlp[WPC], rct[WPC];
    __shared__ int   s_last;
    __shared__ float ft[WPC], fc[WPC];

    const float EPS = 1e-8f;
    const float LN2 = 0.6931471805599453f;
    int t = threadIdx.x, w = t >> 5, l = t & 31;
    int s = blockIdx.x * WPC + w;
    int M = n >> 1;

    // rows: a=2s, b=2s+1 (low ranks), c=n-2-2s, d=n-1-2s (high ranks)
    int ra = 2 * s, rbn = 2 * s + 1;
    int rc = n - 2 - 2 * s, rd = n - 1 - 2 * s;
    bool va = (ra  < M);
    bool vb = (rbn < M);
    bool vc = (rc >= M) && (rc < n);
    bool vd = (rd >= M) && (rd < n);

    float ytv[4] = {0.f, 0.f, 0.f, 0.f};
    float uv [4] = {0.f, 0.f, 0.f, 0.f};
    float ev [4] = {-1.f, -1.f, -1.f, -1.f};
    int   clo[4] = {0, 0, 0, 0};
    int   chi[4] = {0, 0, 0, 0};
    int   rr [4] = {ra, rbn, rc, rd};
    bool  vv [4] = {va, vb, vc, vd};

    #pragma unroll
    for (int x = 0; x < 4; x++) {
        if (vv[x]) {
            float y = st_yt[rr[x]];
            float2 uz = st_uz[rr[x]];
            ytv[x] = y; uv[x] = uz.x;
            float e = y - EPS;
            ev[x] = e;
            int b = min(NBKT - 1, max(0, (int)floorf(e * (float)NBKT)));
            clo[x] = g_boff[b]; chi[x] = g_boff[b + 1];
        }
    }
    // monotone clamp of fast-end cutoffs (ranks ascending => yt ascending)
    int ca = clo[0];
    int cb = max(clo[1], ca);
    int cc = max(clo[2], cb);
    int cd = max(clo[3], cc);
    int Ga = ca >> 2, Gb = cb >> 2, Gc = cc >> 2, Gd = cd >> 2;
    int fe[4] = {Ga << 2, Gb << 2, Gc << 2, Gd << 2};  // fast-covered element ends

    float yA = ytv[0], yB = ytv[1], yC = ytv[2], yD = ytv[3];
    float accA0 = 0.f, accA1 = 0.f, accB0 = 0.f, accB1 = 0.f;
    float accC0 = 0.f, accC1 = 0.f, accD0 = 0.f, accD1 = 0.f;

    const float4* uz4 = (const float4*)st_uz;

    // region 1: [0, Ga) -- all 4 rows fast
    #pragma unroll 2
    for (int g = l; g < Ga; g += 32) {
        float4 p0 = uz4[2 * g], p1 = uz4[2 * g + 1];
        accA0 += ex2a(fmaf(yA, p0.x, p0.y));
        accA1 += ex2a(fmaf(yA, p0.z, p0.w));
        accA0 += ex2a(fmaf(yA, p1.x, p1.y));
        accA1 += ex2a(fmaf(yA, p1.z, p1.w));
        accB0 += ex2a(fmaf(yB, p0.x, p0.y));
        accB1 += ex2a(fmaf(yB, p0.z, p0.w));
        accB0 += ex2a(fmaf(yB, p1.x, p1.y));
        accB1 += ex2a(fmaf(yB, p1.z, p1.w));
        accC0 += ex2a(fmaf(yC, p0.x, p0.y));
        accC1 += ex2a(fmaf(yC, p0.z, p0.w));
        accC0 += ex2a(fmaf(yC, p1.x, p1.y));
        accC1 += ex2a(fmaf(yC, p1.z, p1.w));
        accD0 += ex2a(fmaf(yD, p0.x, p0.y));
        accD1 += ex2a(fmaf(yD, p0.z, p0.w));
        accD0 += ex2a(fmaf(yD, p1.x, p1.y));
        accD1 += ex2a(fmaf(yD, p1.z, p1.w));
    }
    // region 2: [Ga, Gb) -- rows b,c,d (tiny: ranks adjacent)
    for (int g = Ga + l; g < Gb; g += 32) {
        float4 p0 = uz4[2 * g], p1 = uz4[2 * g + 1];
        accB0 += ex2a(fmaf(yB, p0.x, p0.y));
        accB1 += ex2a(fmaf(yB, p0.z, p0.w));
        accB0 += ex2a(fmaf(yB, p1.x, p1.y));
        accB1 += ex2a(fmaf(yB, p1.z, p1.w));
        accC0 += ex2a(fmaf(yC, p0.x, p0.y));
        accC1 += ex2a(fmaf(yC, p0.z, p0.w));
        accC0 += ex2a(fmaf(yC, p1.x, p1.y));
        accC1 += ex2a(fmaf(yC, p1.z, p1.w));
        accD0 += ex2a(fmaf(yD, p0.x, p0.y));
        accD1 += ex2a(fmaf(yD, p0.z, p0.w));
        accD0 += ex2a(fmaf(yD, p1.x, p1.y));
        accD1 += ex2a(fmaf(yD, p1.z, p1.w));
    }
    // region 3: [Gb, Gc) -- rows c,d (big)
    #pragma unroll 2
    for (int g = Gb + l; g < Gc; g += 32) {
        float4 p0 = uz4[2 * g], p1 = uz4[2 * g + 1];
        accC0 += ex2a(fmaf(yC, p0.x, p0.y));
        accC1 += ex2a(fmaf(yC, p0.z, p0.w));
        accC0 += ex2a(fmaf(yC, p1.x, p1.y));
        accC1 += ex2a(fmaf(yC, p1.z, p1.w));
        accD0 += ex2a(fmaf(yD, p0.x, p0.y));
        accD1 += ex2a(fmaf(yD, p0.z, p0.w));
        accD0 += ex2a(fmaf(yD, p1.x, p1.y));
        accD1 += ex2a(fmaf(yD, p1.z, p1.w));
    }
    // region 4: [Gc, Gd) -- row d only (tiny)
    for (int g = Gc + l; g < Gd; g += 32) {
        float4 p0 = uz4[2 * g], p1 = uz4[2 * g + 1];
        accD0 += ex2a(fmaf(yD, p0.x, p0.y));
        accD1 += ex2a(fmaf(yD, p0.z, p0.w));
        accD0 += ex2a(fmaf(yD, p1.x, p1.y));
        accD1 += ex2a(fmaf(yD, p1.z, p1.w));
    }

    // masked leftovers per row: elements [fe[x], chi[x]) with predicate
    float accM[4] = {0.f, 0.f, 0.f, 0.f};
    #pragma unroll
    for (int x = 0; x < 4; x++) {
        float yx = ytv[x], ex = ev[x];
        for (int i = fe[x] + l; i < chi[x]; i += 32) {
            float2 uz = st_uz[i];
            float  yv = st_yt[i];
            float  v  = ex2a(fmaf(yx, uz.x, uz.y));
            if (yv < ex) accM[x] += v;
        }
    }

    // warp reductions (full warp, full mask)
    float sR[4];
    sR[0] = accA0 + accA1 + accM[0];
    sR[1] = accB0 + accB1 + accM[1];
    sR[2] = accC0 + accC1 + accM[2];
    sR[3] = accD0 + accD1 + accM[3];
    #pragma unroll
    for (int o = 16; o; o >>= 1) {
        sR[0] += __shfl_xor_sync(0xffffffffu, sR[0], o);
        sR[1] += __shfl_xor_sync(0xffffffffu, sR[1], o);
        sR[2] += __shfl_xor_sync(0xffffffffu, sR[2], o);
        sR[3] += __shfl_xor_sync(0xffffffffu, sR[3], o);
    }

    if (l == 0) {
        float lp = 0.f, c = 0.f;
        float ymin = g_ymin;
        #pragma unroll
        for (int x = 0; x < 4; x++) {
            if (vv[x]) {
                float d = ytv[x] - ymin;
                if (d > EPS) {
                    float wv = uv[x] * d;               // log2 of exp(logit_pos)
                    lp += wv * LN2 - logf(ex2a(wv) + sR[x]);
                    c  += 1.f;
                }
            }
        }
        rlp[w] = lp; rct[w] = c;
    }
    __syncthreads();

    // publish per-CTA partial, elect last block
    if (t == 0) {
        float tot = 0.f, c = 0.f;
        #pragma unroll
        for (int i = 0; i < WPC; i++) { tot += rlp[i]; c += rct[i]; }
        g_part[blockIdx.x] = make_float2(tot, c);
        __threadfence();
        int done = atomicAdd(&g_done, 1);
        s_last = (done == grid - 1) ? 1 : 0;
    }
    __syncthreads();

    // last block: deterministic final reduce
    if (s_last) {
        __threadfence();
        float tot = 0.f, cnt = 0.f;
        for (int i = t; i < grid; i += TPB) {
            float2 p = g_part[i]; tot += p.x; cnt += p.y;
        }
        #pragma unroll
        for (int o = 16; o; o >>= 1) {            // all threads, full warps
            tot += __shfl_xor_sync(0xffffffffu, tot, o);
            cnt += __shfl_xor_sync(0xffffffffu, cnt, o);
        }
        if ((t & 31) == 0) { ft[t >> 5] = tot; fc[t >> 5] = cnt; }
        __syncthreads();
        if (t == 0) {
            float a = 0.f, b = 0.f;
            #pragma unroll
            for (int i = 0; i < WPC; i++) { a += ft[i]; b += fc[i]; }
            out[0] = (b > 0.f) ? (-a / b) : 0.0f;
            g_done = 0;   // restore for next graph replay
        }
    }
}

// ------------- Launch --------------------------------------------------------
extern "C" void kernel_launch(void* const* d_in, const int* in_sizes, int n_in,
                              void* d_out, int out_size)
{
    const float* pred = (const float*)d_in[0];   // predict_similarity
    const float* yt   = (const float*)d_in[1];   // true_similarity
    int n = in_sizes[0];
    if (n > NMAX) n = NMAX;
    int padn = (n + 7) & ~7;
    if (padn > NMAX) padn = NMAX;

    int nslots = (n + 3) / 4;                    // 2048 four-row slots for n=8192
    int grid = (nslots + WPC - 1) / WPC;         // 147 -> one CTA per SM, one wave
    if (grid > GMAX) grid = GMAX;

    pro_prep<<<1, 1024>>>(pred, yt, n, padn);
    pro_main<<<grid, TPB>>>((float*)d_out, n, grid);
}

// round 13
// speedup vs baseline: 1.0577x; 1.0577x over previous
#include <cuda_runtime.h>
#include <math.h>

#define NMAX  8192
#define NBKT  1024
#define TPB   896     // 28 warps; 2 warps = 1 row-pair slot (j-split halves)
#define SPC   14      // slots per CTA
#define GMAX  512

__device__ float2 st_uz[NMAX];        // sorted-by-yt: (u = yp*20*log2e, z = -u*yt)
__device__ float  st_yt[NMAX];        // sorted yt
__device__ int    g_boff[NBKT + 1];   // bucket rank offsets
__device__ float  g_ymin;
__device__ float2 g_part[GMAX];
__device__ int    g_done;             // zero-init; reset by last block each run

__device__ __forceinline__ float ex2a(float x) {
    float r; asm("ex2.approx.f32 %0, %1;" : "=f"(r) : "f"(x)); return r;
}

// ------------- Prep: counting sort staged through smem ----------------------
__global__ void __launch_bounds__(1024) pro_prep(const float* __restrict__ pred,
                                                 const float* __restrict__ ytg,
                                                 int n, int padn)
{
    __shared__ int   HA[NBKT], HB[NBKT];   // 8 KB
    __shared__ float SG[NMAX];             // 32 KB stage
    __shared__ float smn[32];
    const float K1 = 28.853900817779268f;  // 20 * log2(e)
    int t = threadIdx.x;

    HA[t] = 0;
    __syncthreads();

    float ry[8], rp[8];
    int   rb[8], rpos[8];
    float mn = 1e30f;

    #pragma unroll
    for (int e = 0; e < 8; e++) {
        int i = t + e * 1024;
        if (i < n) {
            float y = ytg[i], p = pred[i];
            ry[e] = y; rp[e] = p;
            int b = min(NBKT - 1, max(0, (int)floorf(y * (float)NBKT)));
            rb[e] = b;
            atomicAdd(&HA[b], 1);
            mn = fminf(mn, y);
        } else { ry[e] = 0.f; rp[e] = 0.f; rb[e] = -1; }
    }
    __syncthreads();

    int* pa = HA; int* pb = HB;
    #pragma unroll
    for (int off = 1; off < NBKT; off <<= 1) {
        pb[t] = pa[t] + ((t >= off) ? pa[t - off] : 0);
        __syncthreads();
        int* tmp = pa; pa = pb; pb = tmp;
    }
    if (t == 0) g_boff[0] = 0;
    g_boff[t + 1] = pa[t];
    pb[t] = (t > 0) ? pa[t - 1] : 0;       // per-bucket running cursors
    __syncthreads();

    #pragma unroll
    for (int e = 0; e < 8; e++)
        if (rb[e] >= 0) rpos[e] = atomicAdd(&pb[rb[e]], 1);
    __syncthreads();

    float* uzf = (float*)st_uz;
    // pass 1: u (interleaved slot .x)
    #pragma unroll
    for (int e = 0; e < 8; e++) if (rb[e] >= 0) SG[rpos[e]] = rp[e] * K1;
    __syncthreads();
    #pragma unroll
    for (int e = 0; e < 8; e++) { int i = t + e * 1024; if (i < n) uzf[2 * i] = SG[i]; }
    __syncthreads();
    // pass 2: z = -u*yt (interleaved slot .y)
    #pragma unroll
    for (int e = 0; e < 8; e++) if (rb[e] >= 0) SG[rpos[e]] = -(rp[e] * K1) * ry[e];
    __syncthreads();
    #pragma unroll
    for (int e = 0; e < 8; e++) { int i = t + e * 1024; if (i < n) uzf[2 * i + 1] = SG[i]; }
    __syncthreads();
    // pass 3: yt
    #pragma unroll
    for (int e = 0; e < 8; e++) if (rb[e] >= 0) SG[rpos[e]] = ry[e];
    __syncthreads();
    #pragma unroll
    for (int e = 0; e < 8; e++) { int i = t + e * 1024; if (i < n) st_yt[i] = SG[i]; }
    // padding
    for (int i = n + t; i < padn; i += 1024) {
        uzf[2 * i] = 0.f; uzf[2 * i + 1] = 0.f; st_yt[i] = 1e30f;
    }

    // global min
    #pragma unroll
    for (int o = 16; o; o >>= 1) mn = fminf(mn, __shfl_xor_sync(0xffffffffu, mn, o));
    if ((t & 31) == 0) smn[t >> 5] = mn;
    __syncthreads();
    if (t < 32) {
        float v = smn[t];
        #pragma unroll
        for (int o = 16; o; o >>= 1) v = fminf(v, __shfl_xor_sync(0xffffffffu, v, o));
        if (t == 0) g_ymin = v;
    }
}

// ------------- Main: 2 warps per slot (j-split), 56 warps/SM -----------------
__global__ void __launch_bounds__(TPB) pro_main(float* __restrict__ out,
                                                int n, int grid)
{
    __shared__ float sAh[TPB / 32], sBh[TPB / 32];   // per-warp partials
    __shared__ float rlp[SPC], rct[SPC];
    __shared__ int   s_last;
    __shared__ float ft[TPB / 32], fc[TPB / 32];

    const float EPS = 1e-8f;
    const float LN2 = 0.6931471805599453f;
    int t = threadIdx.x, w = t >> 5, l = t & 31;
    int h = w & 1;                         // which half of the j-range
    int q = blockIdx.x * SPC + (w >> 1);   // row-pair slot

    bool hasA = (2 * q <= n - 1);
    bool hasB = (2 * q <  n - 1);
    int rA = q, rB = n - 1 - q;

    float ytA = 0.f, eA = 0.f; int cLoA = 0, cHiA = 0;
    float ytB = 0.f, eB = 0.f; int cLoB = 0, cHiB = 0;
    if (hasA) {
        ytA = st_yt[rA]; eA = ytA - EPS;
        int b = min(NBKT - 1, max(0, (int)floorf(eA * (float)NBKT)));
        cLoA = g_boff[b]; cHiA = g_boff[b + 1];
    }
    if (hasB) {
        ytB = st_yt[rB]; eB = ytB - EPS;
        int b = min(NBKT - 1, max(0, (int)floorf(eB * (float)NBKT)));
        cLoB = g_boff[b]; cHiB = g_boff[b + 1];
    } else { ytB = ytA; eB = eA; cLoB = cLoA; cHiB = cLoA; }

    float aA = 0.f, aA2 = 0.f, aB = 0.f, aB2 = 0.f;
    const float4* uz4 = (const float4*)st_uz;
    const float4* yt4 = (const float4*)st_yt;

    int G1  = cLoA >> 2;            // groups fully valid for BOTH rows
    int G2  = cLoB >> 2;            // groups fully valid for B
    int GHA = (cHiA + 3) >> 2;
    int GHB = (cHiB + 3) >> 2;

    int off = (h << 5) + l;         // 0..63: this warp-half's lane offset

    if (hasA) {
        // shared fast loop: 8 exps per 2 loads, no masks
        #pragma unroll 2
        for (int g = off; g < G1; g += 64) {
            float4 p0 = uz4[2 * g], p1 = uz4[2 * g + 1];
            aA  += ex2a(fmaf(ytA, p0.x, p0.y));
            aA2 += ex2a(fmaf(ytA, p0.z, p0.w));
            aA  += ex2a(fmaf(ytA, p1.x, p1.y));
            aA2 += ex2a(fmaf(ytA, p1.z, p1.w));
            aB  += ex2a(fmaf(ytB, p0.x, p0.y));
            aB2 += ex2a(fmaf(ytB, p0.z, p0.w));
            aB  += ex2a(fmaf(ytB, p1.x, p1.y));
            aB2 += ex2a(fmaf(ytB, p1.z, p1.w));
        }
        // B-only fast loop
        #pragma unroll 2
        for (int g = G1 + off; g < G2; g += 64) {
            float4 p0 = uz4[2 * g], p1 = uz4[2 * g + 1];
            aB  += ex2a(fmaf(ytB, p0.x, p0.y));
            aB2 += ex2a(fmaf(ytB, p0.z, p0.w));
            aB  += ex2a(fmaf(ytB, p1.x, p1.y));
            aB2 += ex2a(fmaf(ytB, p1.z, p1.w));
        }
        // A masked bucket (tiny)
        for (int g = G1 + off; g < GHA; g += 64) {
            float4 p0 = uz4[2 * g], p1 = uz4[2 * g + 1];
            float4 y0 = yt4[g];
            float v0 = ex2a(fmaf(ytA, p0.x, p0.y));
            float v1 = ex2a(fmaf(ytA, p0.z, p0.w));
            float v2 = ex2a(fmaf(ytA, p1.x, p1.y));
            float v3 = ex2a(fmaf(ytA, p1.z, p1.w));
            if (y0.x < eA) aA  += v0;
            if (y0.y < eA) aA2 += v1;
            if (y0.z < eA) aA  += v2;
            if (y0.w < eA) aA2 += v3;
        }
        // B masked bucket (tiny)
        for (int g = G2 + off; g < GHB; g += 64) {
            float4 p0 = uz4[2 * g], p1 = uz4[2 * g + 1];
            float4 y0 = yt4[g];
            float v0 = ex2a(fmaf(ytB, p0.x, p0.y));
            float v1 = ex2a(fmaf(ytB, p0.z, p0.w));
            float v2 = ex2a(fmaf(ytB, p1.x, p1.y));
            float v3 = ex2a(fmaf(ytB, p1.z, p1.w));
            if (y0.x < eB) aB  += v0;
            if (y0.y < eB) aB2 += v1;
            if (y0.z < eB) aB  += v2;
            if (y0.w < eB) aB2 += v3;
        }
    }

    // warp reduce (full warp, full mask)
    float sA = aA + aA2;
    float sB = aB + aB2;
    #pragma unroll
    for (int o = 16; o; o >>= 1) {
        sA += __shfl_xor_sync(0xffffffffu, sA, o);
        sB += __shfl_xor_sync(0xffffffffu, sB, o);
    }
    if (l == 0) { sAh[w] = sA; sBh[w] = sB; }
    __syncthreads();

    // combine the two half-warps of each slot; compute per-slot logprob
    if (t < SPC) {
        int qq = blockIdx.x * SPC + t;
        bool hA = (2 * qq <= n - 1);
        bool hB = (2 * qq <  n - 1);
        float lp = 0.f, c = 0.f;
        if (hA) {
            float ymin = g_ymin;
            float sAt = sAh[2 * t] + sAh[2 * t + 1];
            float sBt = sBh[2 * t] + sBh[2 * t + 1];
            float yA2 = st_yt[qq];
            float dA = yA2 - ymin;
            if (dA > EPS) {
                float wv = st_uz[qq].x * dA;
                lp += wv * LN2 - logf(ex2a(wv) + sAt);
                c  += 1.f;
            }
            if (hB) {
                int rB2 = n - 1 - qq;
                float yB2 = st_yt[rB2];
                float dB = yB2 - ymin;
                if (dB > EPS) {
                    float wv = st_uz[rB2].x * dB;
                    lp += wv * LN2 - logf(ex2a(wv) + sBt);
                    c  += 1.f;
                }
            }
        }
        rlp[t] = lp; rct[t] = c;
    }
    __syncthreads();

    // publish per-CTA partial, elect last block
    if (t == 0) {
        float tot = 0.f, c = 0.f;
        #pragma unroll
        for (int i = 0; i < SPC; i++) { tot += rlp[i]; c += rct[i]; }
        g_part[blockIdx.x] = make_float2(tot, c);
        __threadfence();
        int done = atomicAdd(&g_done, 1);
        s_last = (done == grid - 1) ? 1 : 0;
    }
    __syncthreads();

    // last block: deterministic final reduce
    if (s_last) {
        __threadfence();
        float tot = 0.f, cnt = 0.f;
        for (int i = t; i < grid; i += TPB) {
            float2 p = g_part[i]; tot += p.x; cnt += p.y;
        }
        #pragma unroll
        for (int o = 16; o; o >>= 1) {            // all threads, full warps
            tot += __shfl_xor_sync(0xffffffffu, tot, o);
            cnt += __shfl_xor_sync(0xffffffffu, cnt, o);
        }
        if ((t & 31) == 0) { ft[t >> 5] = tot; fc[t >> 5] = cnt; }
        __syncthreads();
        if (t == 0) {
            float a = 0.f, b = 0.f;
            #pragma unroll
            for (int i = 0; i < TPB / 32; i++) { a += ft[i]; b += fc[i]; }
            out[0] = (b > 0.f) ? (-a / b) : 0.0f;
            g_done = 0;   // restore for next graph replay
        }
    }
}

// ------------- Launch --------------------------------------------------------
extern "C" void kernel_launch(void* const* d_in, const int* in_sizes, int n_in,
                              void* d_out, int out_size)
{
    const float* pred = (const float*)d_in[0];   // predict_similarity
    const float* yt   = (const float*)d_in[1];   // true_similarity
    int n = in_sizes[0];
    if (n > NMAX) n = NMAX;
    int padn = (n + 7) & ~7;
    if (padn > NMAX) padn = NMAX;

    int nslots = (n + 1) / 2;                    // 4096 row-pair slots
    int grid = (nslots + SPC - 1) / SPC;         // 293 CTAs -> ~2 per SM, 56 warps/SM
    if (grid > GMAX) grid = GMAX;

    pro_prep<<<1, 1024>>>(pred, yt, n, padn);
    pro_main<<<grid, TPB>>>((float*)d_out, n, grid);
}

// round 14
// speedup vs baseline: 1.0712x; 1.0127x over previous
#include <cuda_runtime.h>
#include <math.h>

#define NMAX  8192
#define NBKT  1024
#define TPB   896     // 28 warps; 1 warp = 1 row-pair slot
#define SLOTS 28
#define GMAX  512
#define SMEM_BYTES (NMAX * 2 * sizeof(float))   // 64 KB staged (u,z)

__device__ float2 st_uz[NMAX];        // sorted-by-yt: (u = yp*20*log2e, z = -u*yt)
__device__ float  st_yt[NMAX];        // sorted yt
__device__ int    g_boff[NBKT + 1];   // bucket rank offsets
__device__ float  g_ymin;
__device__ float2 g_part[GMAX];
__device__ int    g_done;             // zero-init; reset by last block each run

__device__ __forceinline__ float ex2a(float x) {
    float r; asm("ex2.approx.f32 %0, %1;" : "=f"(r) : "f"(x)); return r;
}

// ------------- Prep: counting sort staged through smem ----------------------
__global__ void __launch_bounds__(1024) pro_prep(const float* __restrict__ pred,
                                                 const float* __restrict__ ytg,
                                                 int n, int padn)
{
    __shared__ int   HA[NBKT], HB[NBKT];   // 8 KB
    __shared__ float SG[NMAX];             // 32 KB stage
    __shared__ float smn[32];
    const float K1 = 28.853900817779268f;  // 20 * log2(e)
    int t = threadIdx.x;

    HA[t] = 0;
    __syncthreads();

    float ry[8], rp[8];
    int   rb[8], rpos[8];
    float mn = 1e30f;

    #pragma unroll
    for (int e = 0; e < 8; e++) {
        int i = t + e * 1024;
        if (i < n) {
            float y = ytg[i], p = pred[i];
            ry[e] = y; rp[e] = p;
            int b = min(NBKT - 1, max(0, (int)floorf(y * (float)NBKT)));
            rb[e] = b;
            atomicAdd(&HA[b], 1);
            mn = fminf(mn, y);
        } else { ry[e] = 0.f; rp[e] = 0.f; rb[e] = -1; }
    }
    __syncthreads();

    int* pa = HA; int* pb = HB;
    #pragma unroll
    for (int off = 1; off < NBKT; off <<= 1) {
        pb[t] = pa[t] + ((t >= off) ? pa[t - off] : 0);
        __syncthreads();
        int* tmp = pa; pa = pb; pb = tmp;
    }
    if (t == 0) g_boff[0] = 0;
    g_boff[t + 1] = pa[t];
    pb[t] = (t > 0) ? pa[t - 1] : 0;       // per-bucket running cursors
    __syncthreads();

    #pragma unroll
    for (int e = 0; e < 8; e++)
        if (rb[e] >= 0) rpos[e] = atomicAdd(&pb[rb[e]], 1);
    __syncthreads();

    float* uzf = (float*)st_uz;
    // pass 1: u (interleaved slot .x)
    #pragma unroll
    for (int e = 0; e < 8; e++) if (rb[e] >= 0) SG[rpos[e]] = rp[e] * K1;
    __syncthreads();
    #pragma unroll
    for (int e = 0; e < 8; e++) { int i = t + e * 1024; if (i < n) uzf[2 * i] = SG[i]; }
    __syncthreads();
    // pass 2: z = -u*yt (interleaved slot .y)
    #pragma unroll
    for (int e = 0; e < 8; e++) if (rb[e] >= 0) SG[rpos[e]] = -(rp[e] * K1) * ry[e];
    __syncthreads();
    #pragma unroll
    for (int e = 0; e < 8; e++) { int i = t + e * 1024; if (i < n) uzf[2 * i + 1] = SG[i]; }
    __syncthreads();
    // pass 3: yt
    #pragma unroll
    for (int e = 0; e < 8; e++) if (rb[e] >= 0) SG[rpos[e]] = ry[e];
    __syncthreads();
    #pragma unroll
    for (int e = 0; e < 8; e++) { int i = t + e * 1024; if (i < n) st_yt[i] = SG[i]; }
    // padding
    for (int i = n + t; i < padn; i += 1024) {
        uzf[2 * i] = 0.f; uzf[2 * i + 1] = 0.f; st_yt[i] = 1e30f;
    }

    // global min
    #pragma unroll
    for (int o = 16; o; o >>= 1) mn = fminf(mn, __shfl_xor_sync(0xffffffffu, mn, o));
    if ((t & 31) == 0) smn[t >> 5] = mn;
    __syncthreads();
    if (t < 32) {
        float v = smn[t];
        #pragma unroll
        for (int o = 16; o; o >>= 1) v = fminf(v, __shfl_xor_sync(0xffffffffu, v, o));
        if (t == 0) g_ymin = v;
    }
}

// ------------- Main: one warp per slot, (u,z) staged in smem -----------------
__global__ void __launch_bounds__(TPB) pro_main(float* __restrict__ out,
                                                int n, int padn, int grid)
{
    extern __shared__ __align__(16) char smem_raw[];
    float4* suz4 = (float4*)smem_raw;          // 64 KB: (u,z) pairs, 2 elems/float4

    __shared__ float rlp[SLOTS], rct[SLOTS];
    __shared__ int   s_last;
    __shared__ float ft[SLOTS], fc[SLOTS];

    const float EPS = 1e-8f;
    const float LN2 = 0.6931471805599453f;
    int t = threadIdx.x, w = t >> 5, l = t & 31;
    int q = blockIdx.x * SLOTS + w;

    // stage the sorted (u,z) array into shared memory once
    {
        const float4* src = (const float4*)st_uz;
        int ngrp = padn >> 1;                   // float4 count
        for (int i = t; i < ngrp; i += TPB) suz4[i] = src[i];
    }

    bool hasA = (2 * q <= n - 1);
    bool hasB = (2 * q <  n - 1);
    int rA = q, rB = n - 1 - q;

    float ytA = 0.f, uA = 0.f, eA = 0.f; int cLoA = 0, cHiA = 0;
    float ytB = 0.f, uB = 0.f, eB = 0.f; int cLoB = 0, cHiB = 0;
    if (hasA) {
        ytA = st_yt[rA]; uA = st_uz[rA].x; eA = ytA - EPS;
        int b = min(NBKT - 1, max(0, (int)floorf(eA * (float)NBKT)));
        cLoA = g_boff[b]; cHiA = g_boff[b + 1];
    }
    if (hasB) {
        ytB = st_yt[rB]; uB = st_uz[rB].x; eB = ytB - EPS;
        int b = min(NBKT - 1, max(0, (int)floorf(eB * (float)NBKT)));
        cLoB = g_boff[b]; cHiB = g_boff[b + 1];
    } else { ytB = ytA; eB = eA; cLoB = cLoA; cHiB = cLoA; }

    __syncthreads();                            // staging complete

    float aA = 0.f, aA2 = 0.f, aB = 0.f, aB2 = 0.f;
    const float4* yt4 = (const float4*)st_yt;   // masked loops only (tiny)

    int G1  = cLoA >> 2;            // groups fully valid for BOTH rows
    int G2  = cLoB >> 2;            // groups fully valid for B
    int GHA = (cHiA + 3) >> 2;
    int GHB = (cHiB + 3) >> 2;

    if (hasA) {
        // shared fast loop: 8 exps per 2 LDS.128, no masks
        #pragma unroll 2
        for (int g = l; g < G1; g += 32) {
            float4 p0 = suz4[2 * g], p1 = suz4[2 * g + 1];
            aA  += ex2a(fmaf(ytA, p0.x, p0.y));
            aA2 += ex2a(fmaf(ytA, p0.z, p0.w));
            aA  += ex2a(fmaf(ytA, p1.x, p1.y));
            aA2 += ex2a(fmaf(ytA, p1.z, p1.w));
            aB  += ex2a(fmaf(ytB, p0.x, p0.y));
            aB2 += ex2a(fmaf(ytB, p0.z, p0.w));
            aB  += ex2a(fmaf(ytB, p1.x, p1.y));
            aB2 += ex2a(fmaf(ytB, p1.z, p1.w));
        }
        // B-only fast loop
        #pragma unroll 2
        for (int g = G1 + l; g < G2; g += 32) {
            float4 p0 = suz4[2 * g], p1 = suz4[2 * g + 1];
            aB  += ex2a(fmaf(ytB, p0.x, p0.y));
            aB2 += ex2a(fmaf(ytB, p0.z, p0.w));
            aB  += ex2a(fmaf(ytB, p1.x, p1.y));
            aB2 += ex2a(fmaf(ytB, p1.z, p1.w));
        }
        // A masked bucket (~1-2 groups)
        for (int g = G1 + l; g < GHA; g += 32) {
            float4 p0 = suz4[2 * g], p1 = suz4[2 * g + 1];
            float4 y0 = yt4[g];
            float v0 = ex2a(fmaf(ytA, p0.x, p0.y));
            float v1 = ex2a(fmaf(ytA, p0.z, p0.w));
            float v2 = ex2a(fmaf(ytA, p1.x, p1.y));
            float v3 = ex2a(fmaf(ytA, p1.z, p1.w));
            if (y0.x < eA) aA  += v0;
            if (y0.y < eA) aA2 += v1;
            if (y0.z < eA) aA  += v2;
            if (y0.w < eA) aA2 += v3;
        }
        // B masked bucket
        for (int g = G2 + l; g < GHB; g += 32) {
            float4 p0 = suz4[2 * g], p1 = suz4[2 * g + 1];
            float4 y0 = yt4[g];
            float v0 = ex2a(fmaf(ytB, p0.x, p0.y));
            float v1 = ex2a(fmaf(ytB, p0.z, p0.w));
            float v2 = ex2a(fmaf(ytB, p1.x, p1.y));
            float v3 = ex2a(fmaf(ytB, p1.z, p1.w));
            if (y0.x < eB) aB  += v0;
            if (y0.y < eB) aB2 += v1;
            if (y0.z < eB) aB  += v2;
            if (y0.w < eB) aB2 += v3;
        }
    }

    // warp reduce (full warp, full mask)
    float sA = aA + aA2;
    float sB = aB + aB2;
    #pragma unroll
    for (int o = 16; o; o >>= 1) {
        sA += __shfl_xor_sync(0xffffffffu, sA, o);
        sB += __shfl_xor_sync(0xffffffffu, sB, o);
    }

    if (l == 0) {
        float lp = 0.f, c = 0.f;
        float ymin = g_ymin;
        if (hasA) {
            float d = ytA - ymin;
            if (d > EPS) {
                float wv = uA * d;                   // log2 of exp(logit_pos)
                lp += wv * LN2 - logf(ex2a(wv) + sA);
                c  += 1.f;
            }
        }
        if (hasB) {
            float d = ytB - ymin;
            if (d > EPS) {
                float wv = uB * d;
                lp += wv * LN2 - logf(ex2a(wv) + sB);
                c  += 1.f;
            }
        }
        rlp[w] = lp; rct[w] = c;
    }
    __syncthreads();

    // publish per-CTA partial, elect last block
    if (t == 0) {
        float tot = 0.f, c = 0.f;
        #pragma unroll
        for (int i = 0; i < SLOTS; i++) { tot += rlp[i]; c += rct[i]; }
        g_part[blockIdx.x] = make_float2(tot, c);
        __threadfence();
        int done = atomicAdd(&g_done, 1);
        s_last = (done == grid - 1) ? 1 : 0;
    }
    __syncthreads();

    // last block: deterministic final reduce
    if (s_last) {
        __threadfence();
        float tot = 0.f, cnt = 0.f;
        for (int i = t; i < grid; i += TPB) {
            float2 p = g_part[i]; tot += p.x; cnt += p.y;
        }
        #pragma unroll
        for (int o = 16; o; o >>= 1) {            // all threads, full warps
            tot += __shfl_xor_sync(0xffffffffu, tot, o);
            cnt += __shfl_xor_sync(0xffffffffu, cnt, o);
        }
        if ((t & 31) == 0) { ft[t >> 5] = tot; fc[t >> 5] = cnt; }
        __syncthreads();
        if (t == 0) {
            float a = 0.f, b = 0.f;
            #pragma unroll
            for (int i = 0; i < SLOTS; i++) { a += ft[i]; b += fc[i]; }
            out[0] = (b > 0.f) ? (-a / b) : 0.0f;
            g_done = 0;   // restore for next graph replay
        }
    }
}

// ------------- Launch --------------------------------------------------------
extern "C" void kernel_launch(void* const* d_in, const int* in_sizes, int n_in,
                              void* d_out, int out_size)
{
    const float* pred = (const float*)d_in[0];   // predict_similarity
    const float* yt   = (const float*)d_in[1];   // true_similarity
    int n = in_sizes[0];
    if (n > NMAX) n = NMAX;
    int padn = (n + 7) & ~7;
    if (padn > NMAX) padn = NMAX;

    int nslots = (n + 1) / 2;                    // 4096 row-pair slots
    int grid = (nslots + SLOTS - 1) / SLOTS;     // 147 -> one CTA per SM, one wave
    if (grid > GMAX) grid = GMAX;

    // allow 64 KB dynamic smem (host-side attribute; not a stream op)
    static int smem_set = 0;
    if (!smem_set) {
        cudaFuncSetAttribute(pro_main, cudaFuncAttributeMaxDynamicSharedMemorySize,
                             (int)SMEM_BYTES);
        smem_set = 1;
    }

    pro_prep<<<1, 1024>>>(pred, yt, n, padn);
    pro_main<<<grid, TPB, SMEM_BYTES>>>((float*)d_out, n, padn, grid);
}

// round 15
// speedup vs baseline: 1.3894x; 1.2971x over previous
#include <cuda_runtime.h>
#include <math.h>

#define NMAX  8192
#define NBKT  1024
#define TPB   896     // 28 warps; 1 warp = 1 row-pair slot
#define SLOTS 28
#define GMAX  512
#define SMEM_BYTES (NMAX * 2 * sizeof(float))   // 64 KB: su (32K) + sz (32K)

__device__ float st_u [NMAX];         // sorted-by-yt: u = yp*20*log2e
__device__ float st_z [NMAX];         // z = -u*yt
__device__ float st_yt[NMAX];         // sorted yt
__device__ int   g_boff[NBKT + 1];    // bucket rank offsets
__device__ float g_ymin;
__device__ float2 g_part[GMAX];
__device__ int   g_done;              // zero-init; reset by last block each run

__device__ __forceinline__ float ex2a(float x) {
    float r; asm("ex2.approx.f32 %0, %1;" : "=f"(r) : "f"(x)); return r;
}

// ------------- Prep: counting sort staged through smem ----------------------
__global__ void __launch_bounds__(1024) pro_prep(const float* __restrict__ pred,
                                                 const float* __restrict__ ytg,
                                                 int n, int padn)
{
    __shared__ int   HA[NBKT], HB[NBKT];   // 8 KB
    __shared__ float SG[NMAX];             // 32 KB stage
    __shared__ float smn[32];
    const float K1 = 28.853900817779268f;  // 20 * log2(e)
    int t = threadIdx.x;

    HA[t] = 0;
    __syncthreads();

    float ry[8], rp[8];
    int   rb[8], rpos[8];
    float mn = 1e30f;

    #pragma unroll
    for (int e = 0; e < 8; e++) {
        int i = t + e * 1024;
        if (i < n) {
            float y = ytg[i], p = pred[i];
            ry[e] = y; rp[e] = p;
            int b = min(NBKT - 1, max(0, (int)floorf(y * (float)NBKT)));
            rb[e] = b;
            atomicAdd(&HA[b], 1);
            mn = fminf(mn, y);
        } else { ry[e] = 0.f; rp[e] = 0.f; rb[e] = -1; }
    }
    __syncthreads();

    int* pa = HA; int* pb = HB;
    #pragma unroll
    for (int off = 1; off < NBKT; off <<= 1) {
        pb[t] = pa[t] + ((t >= off) ? pa[t - off] : 0);
        __syncthreads();
        int* tmp = pa; pa = pb; pb = tmp;
    }
    if (t == 0) g_boff[0] = 0;
    g_boff[t + 1] = pa[t];
    pb[t] = (t > 0) ? pa[t - 1] : 0;       // per-bucket running cursors
    __syncthreads();

    #pragma unroll
    for (int e = 0; e < 8; e++)
        if (rb[e] >= 0) rpos[e] = atomicAdd(&pb[rb[e]], 1);
    __syncthreads();

    // pass 1: u
    #pragma unroll
    for (int e = 0; e < 8; e++) if (rb[e] >= 0) SG[rpos[e]] = rp[e] * K1;
    __syncthreads();
    #pragma unroll
    for (int e = 0; e < 8; e++) { int i = t + e * 1024; if (i < n) st_u[i] = SG[i]; }
    __syncthreads();
    // pass 2: z = -u*yt
    #pragma unroll
    for (int e = 0; e < 8; e++) if (rb[e] >= 0) SG[rpos[e]] = -(rp[e] * K1) * ry[e];
    __syncthreads();
    #pragma unroll
    for (int e = 0; e < 8; e++) { int i = t + e * 1024; if (i < n) st_z[i] = SG[i]; }
    __syncthreads();
    // pass 3: yt
    #pragma unroll
    for (int e = 0; e < 8; e++) if (rb[e] >= 0) SG[rpos[e]] = ry[e];
    __syncthreads();
    #pragma unroll
    for (int e = 0; e < 8; e++) { int i = t + e * 1024; if (i < n) st_yt[i] = SG[i]; }
    // padding
    for (int i = n + t; i < padn; i += 1024) { st_u[i] = 0.f; st_z[i] = 0.f; st_yt[i] = 1e30f; }

    // global min
    #pragma unroll
    for (int o = 16; o; o >>= 1) mn = fminf(mn, __shfl_xor_sync(0xffffffffu, mn, o));
    if ((t & 31) == 0) smn[t >> 5] = mn;
    __syncthreads();
    if (t < 32) {
        float v = smn[t];
        #pragma unroll
        for (int o = 16; o; o >>= 1) v = fminf(v, __shfl_xor_sync(0xffffffffu, v, o));
        if (t == 0) g_ymin = v;
    }
}

// ------------- Main: one warp per slot, separate u/z smem (conflict-free) ----
__global__ void __launch_bounds__(TPB) pro_main(float* __restrict__ out,
                                                int n, int padn, int grid)
{
    extern __shared__ __align__(16) char smem_raw[];
    float4* su4 = (float4*)smem_raw;                    // 32 KB u
    float4* sz4 = (float4*)(smem_raw + NMAX * 4);       // 32 KB z

    __shared__ float rlp[SLOTS], rct[SLOTS];
    __shared__ int   s_last;
    __shared__ float ft[SLOTS], fc[SLOTS];

    const float EPS = 1e-8f;
    const float LN2 = 0.6931471805599453f;
    int t = threadIdx.x, w = t >> 5, l = t & 31;
    int q = blockIdx.x * SLOTS + w;

    // stage sorted u and z into separate smem arrays (conflict-free layout)
    {
        const float4* gu = (const float4*)st_u;
        const float4* gz = (const float4*)st_z;
        int ngrp = padn >> 2;
        for (int i = t; i < ngrp; i += TPB) { su4[i] = gu[i]; sz4[i] = gz[i]; }
    }

    bool hasA = (2 * q <= n - 1);
    bool hasB = (2 * q <  n - 1);
    int rA = q, rB = n - 1 - q;

    float ytA = 0.f, uA = 0.f, eA = 0.f; int cLoA = 0, cHiA = 0;
    float ytB = 0.f, uB = 0.f, eB = 0.f; int cLoB = 0, cHiB = 0;
    if (hasA) {
        ytA = st_yt[rA]; uA = st_u[rA]; eA = ytA - EPS;
        int b = min(NBKT - 1, max(0, (int)floorf(eA * (float)NBKT)));
        cLoA = g_boff[b]; cHiA = g_boff[b + 1];
    }
    if (hasB) {
        ytB = st_yt[rB]; uB = st_u[rB]; eB = ytB - EPS;
        int b = min(NBKT - 1, max(0, (int)floorf(eB * (float)NBKT)));
        cLoB = g_boff[b]; cHiB = g_boff[b + 1];
    } else { ytB = ytA; eB = eA; cLoB = cLoA; cHiB = cLoA; }

    __syncthreads();                            // staging complete

    float aA = 0.f, aA2 = 0.f, aB = 0.f, aB2 = 0.f;
    const float4* yt4 = (const float4*)st_yt;   // masked loops only (tiny)

    int G1  = cLoA >> 2;            // groups fully valid for BOTH rows
    int G2  = cLoB >> 2;            // groups fully valid for B
    int GHA = (cHiA + 3) >> 2;
    int GHB = (cHiB + 3) >> 2;

    if (hasA) {
        // shared fast loop: 8 exps per 2 conflict-free LDS.128
        #pragma unroll 2
        for (int g = l; g < G1; g += 32) {
            float4 u0 = su4[g], z0 = sz4[g];
            aA  += ex2a(fmaf(ytA, u0.x, z0.x));
            aA2 += ex2a(fmaf(ytA, u0.y, z0.y));
            aA  += ex2a(fmaf(ytA, u0.z, z0.z));
            aA2 += ex2a(fmaf(ytA, u0.w, z0.w));
            aB  += ex2a(fmaf(ytB, u0.x, z0.x));
            aB2 += ex2a(fmaf(ytB, u0.y, z0.y));
            aB  += ex2a(fmaf(ytB, u0.z, z0.z));
            aB2 += ex2a(fmaf(ytB, u0.w, z0.w));
        }
        // B-only fast loop
        #pragma unroll 2
        for (int g = G1 + l; g < G2; g += 32) {
            float4 u0 = su4[g], z0 = sz4[g];
            aB  += ex2a(fmaf(ytB, u0.x, z0.x));
            aB2 += ex2a(fmaf(ytB, u0.y, z0.y));
            aB  += ex2a(fmaf(ytB, u0.z, z0.z));
            aB2 += ex2a(fmaf(ytB, u0.w, z0.w));
        }
        // A masked bucket (~1-2 groups)
        for (int g = G1 + l; g < GHA; g += 32) {
            float4 u0 = su4[g], z0 = sz4[g], y0 = yt4[g];
            float v0 = ex2a(fmaf(ytA, u0.x, z0.x));
            float v1 = ex2a(fmaf(ytA, u0.y, z0.y));
            float v2 = ex2a(fmaf(ytA, u0.z, z0.z));
            float v3 = ex2a(fmaf(ytA, u0.w, z0.w));
            if (y0.x < eA) aA  += v0;
            if (y0.y < eA) aA2 += v1;
            if (y0.z < eA) aA  += v2;
            if (y0.w < eA) aA2 += v3;
        }
        // B masked bucket
        for (int g = G2 + l; g < GHB; g += 32) {
            float4 u0 = su4[g], z0 = sz4[g], y0 = yt4[g];
            float v0 = ex2a(fmaf(ytB, u0.x, z0.x));
            float v1 = ex2a(fmaf(ytB, u0.y, z0.y));
            float v2 = ex2a(fmaf(ytB, u0.z, z0.z));
            float v3 = ex2a(fmaf(ytB, u0.w, z0.w));
            if (y0.x < eB) aB  += v0;
            if (y0.y < eB) aB2 += v1;
            if (y0.z < eB) aB  += v2;
            if (y0.w < eB) aB2 += v3;
        }
    }

    // warp reduce (full warp, full mask)
    float sA = aA + aA2;
    float sB = aB + aB2;
    #pragma unroll
    for (int o = 16; o; o >>= 1) {
        sA += __shfl_xor_sync(0xffffffffu, sA, o);
        sB += __shfl_xor_sync(0xffffffffu, sB, o);
    }

    if (l == 0) {
        float lp = 0.f, c = 0.f;
        float ymin = g_ymin;
        if (hasA) {
            float d = ytA - ymin;
            if (d > EPS) {
                float wv = uA * d;                   // log2 of exp(logit_pos)
                lp += wv * LN2 - logf(ex2a(wv) + sA);
                c  += 1.f;
            }
        }
        if (hasB) {
            float d = ytB - ymin;
            if (d > EPS) {
                float wv = uB * d;
                lp += wv * LN2 - logf(ex2a(wv) + sB);
                c  += 1.f;
            }
        }
        rlp[w] = lp; rct[w] = c;
    }
    __syncthreads();

    // publish per-CTA partial, elect last block
    if (t == 0) {
        float tot = 0.f, c = 0.f;
        #pragma unroll
        for (int i = 0; i < SLOTS; i++) { tot += rlp[i]; c += rct[i]; }
        g_part[blockIdx.x] = make_float2(tot, c);
        __threadfence();
        int done = atomicAdd(&g_done, 1);
        s_last = (done == grid - 1) ? 1 : 0;
    }
    __syncthreads();

    // last block: deterministic final reduce
    if (s_last) {
        __threadfence();
        float tot = 0.f, cnt = 0.f;
        for (int i = t; i < grid; i += TPB) {
            float2 p = g_part[i]; tot += p.x; cnt += p.y;
        }
        #pragma unroll
        for (int o = 16; o; o >>= 1) {            // all threads, full warps
            tot += __shfl_xor_sync(0xffffffffu, tot, o);
            cnt += __shfl_xor_sync(0xffffffffu, cnt, o);
        }
        if ((t & 31) == 0) { ft[t >> 5] = tot; fc[t >> 5] = cnt; }
        __syncthreads();
        if (t == 0) {
            float a = 0.f, b = 0.f;
            #pragma unroll
            for (int i = 0; i < SLOTS; i++) { a += ft[i]; b += fc[i]; }
            out[0] = (b > 0.f) ? (-a / b) : 0.0f;
            g_done = 0;   // restore for next graph replay
        }
    }
}

// ------------- Launch --------------------------------------------------------
extern "C" void kernel_launch(void* const* d_in, const int* in_sizes, int n_in,
                              void* d_out, int out_size)
{
    const float* pred = (const float*)d_in[0];   // predict_similarity
    const float* yt   = (const float*)d_in[1];   // true_similarity
    int n = in_sizes[0];
    if (n > NMAX) n = NMAX;
    int padn = (n + 7) & ~7;
    if (padn > NMAX) padn = NMAX;

    int nslots = (n + 1) / 2;                    // 4096 row-pair slots
    int grid = (nslots + SLOTS - 1) / SLOTS;     // 147 -> one CTA per SM, one wave
    if (grid > GMAX) grid = GMAX;

    static int smem_set = 0;
    if (!smem_set) {
        cudaFuncSetAttribute(pro_main, cudaFuncAttributeMaxDynamicSharedMemorySize,
                             (int)SMEM_BYTES);
        smem_set = 1;
    }

    pro_prep<<<1, 1024>>>(pred, yt, n, padn);
    pro_main<<<grid, TPB, SMEM_BYTES>>>((float*)d_out, n, padn, grid);
}